// round 16
// baseline (speedup 1.0000x reference)
#include <cuda_runtime.h>
#include <cuda_fp16.h>
#include <math.h>
#include <stdint.h>

#define ROI   116
#define FEAT  6670      // ROI*(ROI-1)/2
#define FEATP 6720      // padded to multiple of 64
#define NB    64        // batch
#define NW    128       // bags per batch
#define BW    8192      // NB*NW
#define DD    1024
#define HH    1024
#define NSTG64 (FEATP / 64)  // 105 K-stages of 64
#define INIT_ELEMS (NB * HH + 2 * HH + 2 * HH + NB * DD)   // 135168
#define INIT_BLOCKS ((INIT_ELEMS + 255) / 256)             // 528

// ---------------- scratch (device globals; no allocation) ----------------
__device__ __align__(16) __half g_bag[(size_t)BW * FEATP];   // 110 MB
__device__ __align__(16) __half g_w1th[(size_t)DD * FEATP];  // 13.8 MB  [N][K]
__device__ __align__(16) int g_off[FEATP];
__device__ float g_a[BW];
__device__ float g_bagz0[NB * FEATP];
__device__ float g_bagz[NB * FEATP];
__device__ float g_ccn[2 * FEATP];
__device__ float g_q[NB * HH];
__device__ float g_k2[2 * HH];
__device__ float g_v2[2 * HH];
__device__ float g_fcx[NB * HH];
__device__ float g_t1[NB * DD];

// ---------------- PTX helpers (generic, sm_80-level) ----------------
__device__ __forceinline__ uint32_t smem_u32(const void* p) {
    uint32_t a;
    asm("{ .reg .u64 t; cvta.to.shared.u64 t, %1; cvt.u32.u64 %0, t; }" : "=r"(a) : "l"(p));
    return a;
}
#define CP_ASYNC16(dst, src) \
    asm volatile("cp.async.cg.shared.global [%0], [%1], 16;" \
                 :: "r"(dst), "l"(src) : "memory")
#define CP_COMMIT() asm volatile("cp.async.commit_group;" ::: "memory")
#define CP_WAIT(n)  asm volatile("cp.async.wait_group %0;" :: "n"(n) : "memory")

__device__ __forceinline__ void ldm_x4(uint32_t& r0, uint32_t& r1, uint32_t& r2, uint32_t& r3,
                                       uint32_t addr) {
    asm volatile("ldmatrix.sync.aligned.m8n8.x4.shared.b16 {%0,%1,%2,%3}, [%4];"
                 : "=r"(r0), "=r"(r1), "=r"(r2), "=r"(r3) : "r"(addr));
}
__device__ __forceinline__ void mma16816(float* c, const uint32_t* a, const uint32_t* b) {
    asm volatile(
        "mma.sync.aligned.m16n8k16.row.col.f32.f16.f16.f32 "
        "{%0,%1,%2,%3}, {%4,%5,%6,%7}, {%8,%9}, {%0,%1,%2,%3};"
        : "+f"(c[0]), "+f"(c[1]), "+f"(c[2]), "+f"(c[3])
        : "r"(a[0]), "r"(a[1]), "r"(a[2]), "r"(a[3]), "r"(b[0]), "r"(b[1]));
}
__device__ __forceinline__ float fast_tanh(float x) {
    float e = __expf(2.0f * x);
    return 1.0f - 2.0f / (e + 1.0f);
}

// ---------------- triu index table + bias-buffer init (fused) -------------
__global__ void init_off_kernel(const float* __restrict__ bq,
                                const float* __restrict__ bk,
                                const float* __restrict__ bc1) {
    int i = blockIdx.x;
    if (i < ROI - 1) {                        // triu table rows
        int base = i * (ROI - 1) - i * (i - 1) / 2;
        int cnt = ROI - 1 - i;
        for (int jj = threadIdx.x; jj < cnt; jj += blockDim.x)
            g_off[base + jj] = i * ROI + (i + 1 + jj);
        return;
    }
    if (i == ROI - 1) {                       // padding
        for (int f = FEAT + threadIdx.x; f < FEATP; f += blockDim.x) g_off[f] = 0;
        return;
    }
    int idx = (i - ROI) * 256 + threadIdx.x;  // bias init region
    if (idx < NB * HH) { g_q[idx] = bq[idx & (HH - 1)]; return; }
    idx -= NB * HH;
    if (idx < 2 * HH) { g_k2[idx] = bk[idx & (HH - 1)]; return; }
    idx -= 2 * HH;
    if (idx < 2 * HH) { g_v2[idx] = bq[idx & (HH - 1)]; return; }
    idx -= 2 * HH;
    if (idx < NB * DD) { g_t1[idx] = bc1[idx & (DD - 1)]; return; }
}

// ---------------- W1 -> W1T fp16 ([N][K], padded); also inits g_a = b2 ----
__global__ void w1t_kernel(const float* __restrict__ W1, const float* __restrict__ b2) {
    __shared__ float t[32][33];
    int kb = blockIdx.x * 32, nb = blockIdx.y * 32;
    int tx = threadIdx.x, ty = threadIdx.y;
    if (blockIdx.x == 0 && blockIdx.y == 0) {
        int tid = ty * 32 + tx;
        float v = b2[0];
        for (int i = tid; i < BW; i += 256) g_a[i] = v;
    }
#pragma unroll
    for (int i = 0; i < 32; i += 8) {
        int k = kb + ty + i;
        t[ty + i][tx] = (k < FEAT) ? W1[(size_t)k * DD + nb + tx] : 0.f;
    }
    __syncthreads();
#pragma unroll
    for (int i = 0; i < 32; i += 8) {
        float v = t[tx][ty + i];
        g_w1th[(size_t)(nb + ty + i) * FEATP + kb + tx] = __float2half_rn(v);
    }
}

// ---------------- gather -> fp16 (8 features per thread, 16B store) -------
__global__ void gather_kernel(const float* __restrict__ FC) {
    int bw = blockIdx.y;
    int f0 = (blockIdx.x * 256 + threadIdx.x) * 8;
    if (f0 >= FEATP) return;
    const float* src = FC + (size_t)bw * (ROI * ROI);
    int4 oa = *reinterpret_cast<const int4*>(g_off + f0);
    int4 ob = *reinterpret_cast<const int4*>(g_off + f0 + 4);
    __half h[8];
    h[0] = (f0 + 0 < FEAT) ? __float2half_rn(src[oa.x]) : __half(0.f);
    h[1] = (f0 + 1 < FEAT) ? __float2half_rn(src[oa.y]) : __half(0.f);
    h[2] = (f0 + 2 < FEAT) ? __float2half_rn(src[oa.z]) : __half(0.f);
    h[3] = (f0 + 3 < FEAT) ? __float2half_rn(src[oa.w]) : __half(0.f);
    h[4] = (f0 + 4 < FEAT) ? __float2half_rn(src[ob.x]) : __half(0.f);
    h[5] = (f0 + 5 < FEAT) ? __float2half_rn(src[ob.y]) : __half(0.f);
    h[6] = (f0 + 6 < FEAT) ? __float2half_rn(src[ob.z]) : __half(0.f);
    h[7] = (f0 + 7 < FEAT) ? __float2half_rn(src[ob.w]) : __half(0.f);
    *reinterpret_cast<float4*>(g_bag + (size_t)bw * FEATP + f0) =
        *reinterpret_cast<const float4*>(h);
}

// ---------------- HMMA GEMM: S = bag @ W1T^T (fp16), fused tanh/W2 epi ----
// CTA 128x64 (N-split to cut wave quantization), 8 warps (4Mx2N),
// warp tile 32x32. K-stage 64, 3-stage pipeline, one sync per stage.
#define LDA       144
#define ATILE_B   18432               // 128 rows x 144B
#define BTILE_B   9216                // 64 rows x 144B
#define STAGE_B   (ATILE_B + BTILE_B) // 27648
#define GEMM_SMEM (3 * STAGE_B)       // 82944

__device__ __forceinline__ void load_stage(uint32_t sdst, int k0, int m0, int n0, int tid) {
    // A: 128 rows x 128B; each thread loads one 64B half-row (4x16B)
    {
        int row = tid >> 1;
        int cb = (tid & 1) * 64;
        uint32_t so = sdst + row * LDA + cb;
        size_t ga = ((size_t)(m0 + row) * FEATP + k0) * 2 + cb;
        unsigned long long pa = __cvta_generic_to_global((const char*)g_bag + ga);
        CP_ASYNC16(so,      pa);      CP_ASYNC16(so + 16, pa + 16);
        CP_ASYNC16(so + 32, pa + 32); CP_ASYNC16(so + 48, pa + 48);
    }
    // B: 64 rows x 128B; each thread loads one 32B quarter-row (2x16B)
    {
        int row = tid >> 2;
        int cb = (tid & 3) * 32;
        uint32_t so = sdst + ATILE_B + row * LDA + cb;
        size_t gb = ((size_t)(n0 + row) * FEATP + k0) * 2 + cb;
        unsigned long long pb = __cvta_generic_to_global((const char*)g_w1th + gb);
        CP_ASYNC16(so, pb); CP_ASYNC16(so + 16, pb + 16);
    }
}

__global__ __launch_bounds__(256, 2) void gemm_mma_kernel(const float* __restrict__ b1,
                                                          const float* __restrict__ W2) {
    extern __shared__ char sm[];
    const uint32_t sbase = smem_u32(sm);
    const int tid = threadIdx.x, lane = tid & 31, wid = tid >> 5;
    const int wm = wid & 3, wn = wid >> 2;        // 4 M-warps x 2 N-warps
    const int n0 = blockIdx.x * 64, m0 = blockIdx.y * 128;

    float acc[2][4][4];
#pragma unroll
    for (int mt = 0; mt < 2; mt++)
#pragma unroll
        for (int nt = 0; nt < 4; nt++)
#pragma unroll
            for (int c = 0; c < 4; c++) acc[mt][nt][c] = 0.f;

    load_stage(sbase, 0, m0, n0, tid);             CP_COMMIT();
    load_stage(sbase + STAGE_B, 64, m0, n0, tid);  CP_COMMIT();

    const uint32_t aRowOfs = (uint32_t)(wm * 32 + ((lane >> 3) & 1) * 8 + (lane & 7)) * LDA
                           + (uint32_t)(lane >> 4) * 16;
    const uint32_t bRowOfs = (uint32_t)(wn * 32 + (lane >> 4) * 8 + (lane & 7)) * LDA
                           + (uint32_t)((lane >> 3) & 1) * 16;

    int slot = 0;
    for (int i = 0; i < NSTG64; i++) {
        if (i + 1 < NSTG64) { CP_WAIT(1); } else { CP_WAIT(0); }
        __syncthreads();
        if (i + 2 < NSTG64) {
            int ns = slot + 2; if (ns >= 3) ns -= 3;
            load_stage(sbase + (uint32_t)ns * STAGE_B, (i + 2) * 64, m0, n0, tid);
            CP_COMMIT();
        }
        const uint32_t st = sbase + (uint32_t)slot * STAGE_B;
#pragma unroll
        for (int kk = 0; kk < 4; kk++) {
            uint32_t aH[2][4], bb[4][2];
#pragma unroll
            for (int mt = 0; mt < 2; mt++)
                ldm_x4(aH[mt][0], aH[mt][1], aH[mt][2], aH[mt][3],
                       st + aRowOfs + (uint32_t)mt * 16 * LDA + kk * 32);
#pragma unroll
            for (int p = 0; p < 2; p++)
                ldm_x4(bb[2 * p][0], bb[2 * p][1], bb[2 * p + 1][0], bb[2 * p + 1][1],
                       st + ATILE_B + bRowOfs + (uint32_t)p * 16 * LDA + kk * 32);
#pragma unroll
            for (int mt = 0; mt < 2; mt++)
#pragma unroll
                for (int nt = 0; nt < 4; nt++) mma16816(acc[mt][nt], aH[mt], bb[nt]);
        }
        if (++slot == 3) slot = 0;
    }

    // epilogue: per-row sum over this 64-col block of tanh(S+b1)*W2
    const int g = lane >> 2, t4 = lane & 3;
#pragma unroll
    for (int mt = 0; mt < 2; mt++) {
        float sA = 0.f, sB = 0.f;
#pragma unroll
        for (int nt = 0; nt < 4; nt++) {
            int c0 = n0 + wn * 32 + nt * 8 + 2 * t4;
            float b1a = b1[c0], b1b = b1[c0 + 1];
            float w2a = W2[c0], w2b = W2[c0 + 1];
            sA += fast_tanh(acc[mt][nt][0] + b1a) * w2a + fast_tanh(acc[mt][nt][1] + b1b) * w2b;
            sB += fast_tanh(acc[mt][nt][2] + b1a) * w2a + fast_tanh(acc[mt][nt][3] + b1b) * w2b;
        }
        sA += __shfl_xor_sync(0xFFFFFFFF, sA, 1);
        sA += __shfl_xor_sync(0xFFFFFFFF, sA, 2);
        sB += __shfl_xor_sync(0xFFFFFFFF, sB, 1);
        sB += __shfl_xor_sync(0xFFFFFFFF, sB, 2);
        if (t4 == 0) {
            int r = m0 + wm * 32 + mt * 16 + g;
            atomicAdd(&g_a[r], sA);
            atomicAdd(&g_a[r + 8], sB);
        }
    }
}

// ---------------- pool with in-block softmax (8 features per thread) ------
__global__ void pool_kernel() {
    int b = blockIdx.y;
    int t = threadIdx.x;
    int f0 = (blockIdx.x * 256 + t) * 8;
    __shared__ float sat[NW];
    __shared__ float red[NW];
    float v = 0.f;
    if (t < NW) { v = g_a[b * NW + t]; red[t] = v; }
    __syncthreads();
    for (int s = 64; s > 0; s >>= 1) { if (t < s) red[t] = fmaxf(red[t], red[t + s]); __syncthreads(); }
    float m = red[0];
    __syncthreads();
    float e = 0.f;
    if (t < NW) { e = expf(v - m); red[t] = e; }
    __syncthreads();
    for (int s = 64; s > 0; s >>= 1) { if (t < s) red[t] += red[t + s]; __syncthreads(); }
    if (t < NW) sat[t] = e / red[0];
    __syncthreads();
    if (f0 >= FEAT) return;
    float a[8];
#pragma unroll
    for (int j = 0; j < 8; j++) a[j] = 0.f;
    const char* base = (const char*)(g_bag + (size_t)b * NW * FEATP + f0);
#pragma unroll 2
    for (int w = 0; w < NW; w++) {
        float4 raw = *reinterpret_cast<const float4*>(base + (size_t)w * (FEATP * 2));
        const __half2* hp = reinterpret_cast<const __half2*>(&raw);
        float aw = sat[w];
#pragma unroll
        for (int j = 0; j < 4; j++) {
            float2 vv = __half22float2(hp[j]);
            a[2 * j]     += aw * vv.x;
            a[2 * j + 1] += aw * vv.y;
        }
    }
    float* dst = g_bagz0 + (size_t)b * FEATP + f0;
    if (f0 + 7 < FEAT) {
        *reinterpret_cast<float4*>(dst)     = make_float4(a[0], a[1], a[2], a[3]);
        *reinterpret_cast<float4*>(dst + 4) = make_float4(a[4], a[5], a[6], a[7]);
    } else {
#pragma unroll
        for (int j = 0; j < 8; j++)
            if (f0 + j < FEAT) dst[j] = a[j];
    }
}

// ---------------- batchnorms ----------------
__global__ void bn_kernel(const float* __restrict__ cc,
                          const float* __restrict__ bn_g, const float* __restrict__ bn_b,
                          const float* __restrict__ bn2_g, const float* __restrict__ bn2_b) {
    int f = blockIdx.x * 256 + threadIdx.x;
    if (f >= FEAT) return;
    float mu = 0.f;
    for (int b = 0; b < NB; b++) mu += g_bagz0[b * FEATP + f];
    mu *= (1.f / NB);
    float var = 0.f;
    for (int b = 0; b < NB; b++) { float d = g_bagz0[b * FEATP + f] - mu; var += d * d; }
    var *= (1.f / NB);
    float inv = rsqrtf(var + 1e-5f);
    float g = bn_g[f], bt = bn_b[f];
    for (int b = 0; b < NB; b++)
        g_bagz[b * FEATP + f] = (g_bagz0[b * FEATP + f] - mu) * inv * g + bt;
    float c0 = cc[f], c1 = cc[FEAT + f];
    float mu2 = 0.5f * (c0 + c1);
    float d0 = c0 - mu2, d1 = c1 - mu2;
    float inv2 = rsqrtf(0.5f * (d0 * d0 + d1 * d1) + 1e-5f);
    float g2 = bn2_g[f], b2v = bn2_b[f];
    g_ccn[f] = d0 * inv2 * g2 + b2v;
    g_ccn[FEATP + f] = d1 * inv2 * g2 + b2v;
}

// ---------------- dual skinny + kv (fused) --------------------------------
__global__ __launch_bounds__(256) void skinny_dual_kernel(const float* __restrict__ B1,
                                                          const float* __restrict__ B2,
                                                          const float* __restrict__ Wk) {
    __shared__ float sA[32][33];
    int tid = threadIdx.x;
    int col = blockIdx.x * 256 + tid;   // < HH (= DD)
    if (blockIdx.z == 2) {
        if (blockIdx.y >= 16) return;
        int len = (FEAT + 15) / 16;
        int k0 = blockIdx.y * len;
        int kend = min(FEAT, k0 + len);
        float ak0 = 0.f, ak1 = 0.f, av0 = 0.f, av1 = 0.f;
        for (int kb = k0; kb < kend; kb += 32) {
            int kmax = min(32, kend - kb);
            if (tid < 64) {
                int m = tid >> 5, kk = tid & 31;
                sA[m][kk] = (kk < kmax) ? g_ccn[(size_t)m * FEATP + kb + kk] : 0.f;
            }
            __syncthreads();
            const float* Kp = Wk + (size_t)kb * HH + col;
            const float* Qp = B1 + (size_t)kb * HH + col;
            int kk = 0;
            for (; kk + 2 <= kmax; kk += 2) {
                float k0v = Kp[0], k1v = Kp[HH];
                float q0v = Qp[0], q1v = Qp[HH];
                Kp += 2 * HH; Qp += 2 * HH;
                ak0 += sA[0][kk] * k0v; ak1 += sA[1][kk] * k0v;
                av0 += sA[0][kk] * q0v; av1 += sA[1][kk] * q0v;
                ak0 += sA[0][kk + 1] * k1v; ak1 += sA[1][kk + 1] * k1v;
                av0 += sA[0][kk + 1] * q1v; av1 += sA[1][kk + 1] * q1v;
            }
            for (; kk < kmax; kk++) {
                float kv = Kp[0], qv = Qp[0]; Kp += HH; Qp += HH;
                ak0 += sA[0][kk] * kv; ak1 += sA[1][kk] * kv;
                av0 += sA[0][kk] * qv; av1 += sA[1][kk] * qv;
            }
            __syncthreads();
        }
        atomicAdd(&g_k2[col], ak0);
        atomicAdd(&g_k2[HH + col], ak1);
        atomicAdd(&g_v2[col], av0);
        atomicAdd(&g_v2[HH + col], av1);
        return;
    }
    int m0 = blockIdx.z * 32;
    int nsplit = gridDim.y;
    int len = (FEAT + nsplit - 1) / nsplit;
    int k0 = blockIdx.y * len;
    int kend = min(FEAT, k0 + len);
    float aq[32], at[32];
#pragma unroll
    for (int m = 0; m < 32; m++) { aq[m] = 0.f; at[m] = 0.f; }
    for (int kb = k0; kb < kend; kb += 32) {
        int kmax = min(32, kend - kb);
        for (int idx = tid; idx < 32 * 32; idx += 256) {
            int m = idx >> 5, kk = idx & 31;
            sA[m][kk] = (kk < kmax) ? g_bagz[(size_t)(m0 + m) * FEATP + kb + kk] : 0.f;
        }
        __syncthreads();
        const float* P1 = B1 + (size_t)kb * HH + col;
        const float* P2 = B2 + (size_t)kb * DD + col;
        int kk = 0;
        for (; kk + 2 <= kmax; kk += 2) {
            float q0 = P1[0], q1 = P1[HH];
            float t0 = P2[0], t1v = P2[DD];
            P1 += 2 * HH; P2 += 2 * DD;
#pragma unroll
            for (int m = 0; m < 32; m++) aq[m] += sA[m][kk] * q0;
#pragma unroll
            for (int m = 0; m < 32; m++) at[m] += sA[m][kk] * t0;
#pragma unroll
            for (int m = 0; m < 32; m++) aq[m] += sA[m][kk + 1] * q1;
#pragma unroll
            for (int m = 0; m < 32; m++) at[m] += sA[m][kk + 1] * t1v;
        }
        for (; kk < kmax; kk++) {
            float q0 = P1[0], t0 = P2[0]; P1 += HH; P2 += DD;
#pragma unroll
            for (int m = 0; m < 32; m++) { aq[m] += sA[m][kk] * q0; at[m] += sA[m][kk] * t0; }
        }
        __syncthreads();
    }
#pragma unroll
    for (int m = 0; m < 32; m++) {
        atomicAdd(&g_q[(size_t)(m0 + m) * HH + col], aq[m]);
        atomicAdd(&g_t1[(size_t)(m0 + m) * DD + col], at[m]);
    }
}

// ---------------- skinny GEMM (fcx part): t1 += fcx@Wc1[0:HH] --------------
__global__ __launch_bounds__(256) void skinny_fcx_kernel(const float* __restrict__ B) {
    __shared__ float sA[64][33];
    int tid = threadIdx.x;
    int col = blockIdx.x * 256 + tid;
    int nsplit = gridDim.y;
    int len = (HH + nsplit - 1) / nsplit;
    int k0 = blockIdx.y * len;
    int kend = min(HH, k0 + len);
    float acc[64];
#pragma unroll
    for (int m = 0; m < 64; m++) acc[m] = 0.f;
    for (int kb = k0; kb < kend; kb += 32) {
        int kmax = min(32, kend - kb);
        for (int idx = tid; idx < 64 * 32; idx += 256) {
            int m = idx >> 5, kk = idx & 31;
            sA[m][kk] = (kk < kmax) ? g_fcx[(size_t)m * HH + kb + kk] : 0.f;
        }
        __syncthreads();
        const float* Bp = B + (size_t)kb * DD + col;
        int kk = 0;
        for (; kk + 4 <= kmax; kk += 4) {
            float bv0 = Bp[0];
            float bv1 = Bp[DD];
            float bv2 = Bp[2 * DD];
            float bv3 = Bp[3 * DD];
            Bp += 4 * (size_t)DD;
#pragma unroll
            for (int m = 0; m < 64; m++) acc[m] += sA[m][kk] * bv0;
#pragma unroll
            for (int m = 0; m < 64; m++) acc[m] += sA[m][kk + 1] * bv1;
#pragma unroll
            for (int m = 0; m < 64; m++) acc[m] += sA[m][kk + 2] * bv2;
#pragma unroll
            for (int m = 0; m < 64; m++) acc[m] += sA[m][kk + 3] * bv3;
        }
        for (; kk < kmax; kk++) {
            float bv = Bp[0]; Bp += (size_t)DD;
#pragma unroll
            for (int m = 0; m < 64; m++) acc[m] += sA[m][kk] * bv;
        }
        __syncthreads();
    }
#pragma unroll
    for (int m = 0; m < 64; m++) atomicAdd(&g_t1[(size_t)m * DD + col], acc[m]);
}

// ---------------- cross attention (64 blocks, one per batch row) ----------
__global__ void cross_kernel() {
    int b = blockIdx.x, t = threadIdx.x;  // 256 threads
    __shared__ float red0[256], red1[256];
    const float* qp = g_q + b * HH;
    float d0 = 0.f, d1 = 0.f;
    for (int d = t; d < HH; d += 256) {
        float qv = qp[d];
        d0 += qv * g_k2[d];
        d1 += qv * g_k2[HH + d];
    }
    red0[t] = d0; red1[t] = d1;
    __syncthreads();
    for (int s = 128; s > 0; s >>= 1) {
        if (t < s) { red0[t] += red0[t + s]; red1[t] += red1[t + s]; }
        __syncthreads();
    }
    float x0 = red0[0] * (1.0f / 32.0f);
    float x1 = red1[0] * (1.0f / 32.0f);
    float m = fmaxf(x0, x1);
    float e0 = expf(x0 - m), e1 = expf(x1 - m);
    float inv = 1.f / (e0 + e1);
    float a0 = e0 * inv, a1 = e1 * inv;
    for (int d = t; d < HH; d += 256)
        g_fcx[b * HH + d] = a0 * g_v2[d] + a1 * g_v2[HH + d];
}

// ---------------- classifier head ----------------
__global__ void final_kernel(const float* __restrict__ Wc2, const float* __restrict__ bc2,
                             float* __restrict__ out, int out_size) {
    int b = blockIdx.x, t = threadIdx.x;
    float acc = 0.f;
    for (int d = t; d < DD; d += 256) acc += fmaxf(g_t1[b * DD + d], 0.f) * Wc2[d];
    __shared__ float red[256];
    red[t] = acc; __syncthreads();
    for (int s = 128; s > 0; s >>= 1) { if (t < s) red[t] += red[t + s]; __syncthreads(); }
    if (t == 0) {
        float y = 1.f / (1.f + expf(-(red[0] + bc2[0])));
        out[b] = y;
        if (64 + b < out_size) out[64 + b] = (y >= 0.5f) ? 1.f : 0.f;
    }
}

// ---------------- launch ----------------
extern "C" void kernel_launch(void* const* d_in, const int* in_sizes, int n_in,
                              void* d_out, int out_size) {
    const float* FC    = (const float*)d_in[0];
    const float* cc    = (const float*)d_in[1];
    const float* W1    = (const float*)d_in[2];
    const float* b1    = (const float*)d_in[3];
    const float* W2    = (const float*)d_in[4];
    const float* b2    = (const float*)d_in[5];
    const float* bn_g  = (const float*)d_in[6];
    const float* bn_b  = (const float*)d_in[7];
    const float* bn2_g = (const float*)d_in[8];
    const float* bn2_b = (const float*)d_in[9];
    const float* Wq    = (const float*)d_in[10];
    const float* bq    = (const float*)d_in[11];
    const float* Wk    = (const float*)d_in[12];
    const float* bk    = (const float*)d_in[13];
    const float* Wc1   = (const float*)d_in[14];
    const float* bc1   = (const float*)d_in[15];
    const float* Wc2   = (const float*)d_in[16];
    const float* bc2   = (const float*)d_in[17];
    float* out = (float*)d_out;

    cudaFuncSetAttribute(gemm_mma_kernel, cudaFuncAttributeMaxDynamicSharedMemorySize, GEMM_SMEM);

    init_off_kernel<<<ROI + INIT_BLOCKS, 256>>>(bq, bk, bc1);               // 1
    w1t_kernel<<<dim3(FEATP / 32, DD / 32), dim3(32, 8)>>>(W1, b2);         // 2
    gather_kernel<<<dim3(4, BW), 256>>>(FC);                                // 3
    gemm_mma_kernel<<<dim3(16, 64), 256, GEMM_SMEM>>>(b1, W2);              // 4 (ncu slot)
    pool_kernel<<<dim3(4, NB), 256>>>();
    bn_kernel<<<(FEAT + 255) / 256, 256>>>(cc, bn_g, bn_b, bn2_g, bn2_b);
    skinny_dual_kernel<<<dim3(4, 104, 3), 256>>>(Wq, Wc1 + (size_t)HH * DD, Wk);
    cross_kernel<<<NB, 256>>>();
    skinny_fcx_kernel<<<dim3(4, 16), 256>>>(Wc1);
    final_kernel<<<NB, 256>>>(Wc2, bc2, out, out_size);
}

// round 17
// speedup vs baseline: 1.4974x; 1.4974x over previous
#include <cuda_runtime.h>
#include <cuda_fp16.h>
#include <math.h>
#include <stdint.h>

#define ROI   116
#define FEAT  6670      // ROI*(ROI-1)/2
#define FEATP 6720      // padded to multiple of 64
#define NB    64        // batch
#define NW    128       // bags per batch
#define BW    8192      // NB*NW
#define DD    1024
#define HH    1024
#define NSTG64 (FEATP / 64)  // 105 K-stages of 64
#define INIT_ELEMS (NB * HH + 2 * HH + 2 * HH + NB * DD)   // 135168
#define INIT_BLOCKS ((INIT_ELEMS + 255) / 256)             // 528

// ---------------- scratch (device globals; no allocation) ----------------
__device__ __align__(16) __half g_bag[(size_t)BW * FEATP];   // 110 MB
__device__ __align__(16) __half g_w1th[(size_t)DD * FEATP];  // 13.8 MB  [N][K]
__device__ __align__(16) int g_off[FEATP];
__device__ float g_a[BW];
__device__ float g_bagz0[NB * FEATP];
__device__ float g_bagz[NB * FEATP];
__device__ float g_ccn[2 * FEATP];
__device__ float g_q[NB * HH];
__device__ float g_k2[2 * HH];
__device__ float g_v2[2 * HH];
__device__ float g_t1[NB * DD];

// ---------------- PTX helpers (generic, sm_80-level) ----------------
__device__ __forceinline__ uint32_t smem_u32(const void* p) {
    uint32_t a;
    asm("{ .reg .u64 t; cvta.to.shared.u64 t, %1; cvt.u32.u64 %0, t; }" : "=r"(a) : "l"(p));
    return a;
}
#define CP_ASYNC16(dst, src) \
    asm volatile("cp.async.cg.shared.global [%0], [%1], 16;" \
                 :: "r"(dst), "l"(src) : "memory")
#define CP_COMMIT() asm volatile("cp.async.commit_group;" ::: "memory")
#define CP_WAIT(n)  asm volatile("cp.async.wait_group %0;" :: "n"(n) : "memory")

__device__ __forceinline__ void ldm_x4(uint32_t& r0, uint32_t& r1, uint32_t& r2, uint32_t& r3,
                                       uint32_t addr) {
    asm volatile("ldmatrix.sync.aligned.m8n8.x4.shared.b16 {%0,%1,%2,%3}, [%4];"
                 : "=r"(r0), "=r"(r1), "=r"(r2), "=r"(r3) : "r"(addr));
}
__device__ __forceinline__ void mma16816(float* c, const uint32_t* a, const uint32_t* b) {
    asm volatile(
        "mma.sync.aligned.m16n8k16.row.col.f32.f16.f16.f32 "
        "{%0,%1,%2,%3}, {%4,%5,%6,%7}, {%8,%9}, {%0,%1,%2,%3};"
        : "+f"(c[0]), "+f"(c[1]), "+f"(c[2]), "+f"(c[3])
        : "r"(a[0]), "r"(a[1]), "r"(a[2]), "r"(a[3]), "r"(b[0]), "r"(b[1]));
}
__device__ __forceinline__ float fast_tanh(float x) {
    float e = __expf(2.0f * x);
    return 1.0f - 2.0f / (e + 1.0f);
}

// ---------------- triu index table + bias-buffer init (fused) -------------
__global__ void init_off_kernel(const float* __restrict__ bq,
                                const float* __restrict__ bk,
                                const float* __restrict__ bc1) {
    int i = blockIdx.x;
    if (i < ROI - 1) {
        int base = i * (ROI - 1) - i * (i - 1) / 2;
        int cnt = ROI - 1 - i;
        for (int jj = threadIdx.x; jj < cnt; jj += blockDim.x)
            g_off[base + jj] = i * ROI + (i + 1 + jj);
        return;
    }
    if (i == ROI - 1) {
        for (int f = FEAT + threadIdx.x; f < FEATP; f += blockDim.x) g_off[f] = 0;
        return;
    }
    int idx = (i - ROI) * 256 + threadIdx.x;
    if (idx < NB * HH) { g_q[idx] = bq[idx & (HH - 1)]; return; }
    idx -= NB * HH;
    if (idx < 2 * HH) { g_k2[idx] = bk[idx & (HH - 1)]; return; }
    idx -= 2 * HH;
    if (idx < 2 * HH) { g_v2[idx] = bq[idx & (HH - 1)]; return; }
    idx -= 2 * HH;
    if (idx < NB * DD) { g_t1[idx] = bc1[idx & (DD - 1)]; return; }
}

// ---------------- W1 -> W1T fp16 ([N][K], padded); also inits g_a = b2 ----
__global__ void w1t_kernel(const float* __restrict__ W1, const float* __restrict__ b2) {
    __shared__ float t[32][33];
    int kb = blockIdx.x * 32, nb = blockIdx.y * 32;
    int tx = threadIdx.x, ty = threadIdx.y;
    if (blockIdx.x == 0 && blockIdx.y == 0) {
        int tid = ty * 32 + tx;
        float v = b2[0];
        for (int i = tid; i < BW; i += 256) g_a[i] = v;
    }
#pragma unroll
    for (int i = 0; i < 32; i += 8) {
        int k = kb + ty + i;
        t[ty + i][tx] = (k < FEAT) ? W1[(size_t)k * DD + nb + tx] : 0.f;
    }
    __syncthreads();
#pragma unroll
    for (int i = 0; i < 32; i += 8) {
        float v = t[tx][ty + i];
        g_w1th[(size_t)(nb + ty + i) * FEATP + kb + tx] = __float2half_rn(v);
    }
}

// ---------------- gather -> fp16 (8 features per thread, 16B store) -------
__global__ void gather_kernel(const float* __restrict__ FC) {
    int bw = blockIdx.y;
    int f0 = (blockIdx.x * 256 + threadIdx.x) * 8;
    if (f0 >= FEATP) return;
    const float* src = FC + (size_t)bw * (ROI * ROI);
    int4 oa = *reinterpret_cast<const int4*>(g_off + f0);
    int4 ob = *reinterpret_cast<const int4*>(g_off + f0 + 4);
    __half h[8];
    h[0] = (f0 + 0 < FEAT) ? __float2half_rn(src[oa.x]) : __half(0.f);
    h[1] = (f0 + 1 < FEAT) ? __float2half_rn(src[oa.y]) : __half(0.f);
    h[2] = (f0 + 2 < FEAT) ? __float2half_rn(src[oa.z]) : __half(0.f);
    h[3] = (f0 + 3 < FEAT) ? __float2half_rn(src[oa.w]) : __half(0.f);
    h[4] = (f0 + 4 < FEAT) ? __float2half_rn(src[ob.x]) : __half(0.f);
    h[5] = (f0 + 5 < FEAT) ? __float2half_rn(src[ob.y]) : __half(0.f);
    h[6] = (f0 + 6 < FEAT) ? __float2half_rn(src[ob.z]) : __half(0.f);
    h[7] = (f0 + 7 < FEAT) ? __float2half_rn(src[ob.w]) : __half(0.f);
    *reinterpret_cast<float4*>(g_bag + (size_t)bw * FEATP + f0) =
        *reinterpret_cast<const float4*>(h);
}

// ---------------- HMMA GEMM: S = bag @ W1T^T (fp16), fused tanh/W2 epi ----
// CTA 128x128, 8 warps (4Mx2N), warp tile 32x64. K-stage 64, 3-stage
// pipeline (CP_WAIT(1)), one __syncthreads per stage. rows 144B. [R15 exact]
#define LDA       144
#define TILE_B    18432               // 128 rows x 144B
#define STAGE_B   (2 * TILE_B)        // A + B = 36864
#define GEMM_SMEM (3 * STAGE_B)       // 110592

__device__ __forceinline__ void load_stage(uint32_t sdst, int k0, int m0, int n0, int tid) {
    int row = tid >> 1;
    int cb = (tid & 1) * 64;
    uint32_t so = sdst + row * LDA + cb;
    size_t ga = ((size_t)(m0 + row) * FEATP + k0) * 2 + cb;
    size_t gb = ((size_t)(n0 + row) * FEATP + k0) * 2 + cb;
    unsigned long long pa = __cvta_generic_to_global((const char*)g_bag + ga);
    unsigned long long pb = __cvta_generic_to_global((const char*)g_w1th + gb);
    CP_ASYNC16(so,      pa);      CP_ASYNC16(so + 16, pa + 16);
    CP_ASYNC16(so + 32, pa + 32); CP_ASYNC16(so + 48, pa + 48);
    so += TILE_B;
    CP_ASYNC16(so,      pb);      CP_ASYNC16(so + 16, pb + 16);
    CP_ASYNC16(so + 32, pb + 32); CP_ASYNC16(so + 48, pb + 48);
}

__global__ __launch_bounds__(256, 2) void gemm_mma_kernel(const float* __restrict__ b1,
                                                          const float* __restrict__ W2) {
    extern __shared__ char sm[];
    const uint32_t sbase = smem_u32(sm);
    const int tid = threadIdx.x, lane = tid & 31, wid = tid >> 5;
    const int wm = wid & 3, wn = wid >> 2;
    const int n0 = blockIdx.x * 128, m0 = blockIdx.y * 128;

    float acc[2][8][4];
#pragma unroll
    for (int mt = 0; mt < 2; mt++)
#pragma unroll
        for (int nt = 0; nt < 8; nt++)
#pragma unroll
            for (int c = 0; c < 4; c++) acc[mt][nt][c] = 0.f;

    load_stage(sbase, 0, m0, n0, tid);             CP_COMMIT();
    load_stage(sbase + STAGE_B, 64, m0, n0, tid);  CP_COMMIT();

    const uint32_t aRowOfs = (uint32_t)(wm * 32 + ((lane >> 3) & 1) * 8 + (lane & 7)) * LDA
                           + (uint32_t)(lane >> 4) * 16;
    const uint32_t bRowOfs = (uint32_t)(wn * 64 + (lane >> 4) * 8 + (lane & 7)) * LDA
                           + (uint32_t)((lane >> 3) & 1) * 16;

    int slot = 0;
    for (int i = 0; i < NSTG64; i++) {
        if (i + 1 < NSTG64) { CP_WAIT(1); } else { CP_WAIT(0); }
        __syncthreads();
        if (i + 2 < NSTG64) {
            int ns = slot + 2; if (ns >= 3) ns -= 3;
            load_stage(sbase + (uint32_t)ns * STAGE_B, (i + 2) * 64, m0, n0, tid);
            CP_COMMIT();
        }
        const uint32_t st = sbase + (uint32_t)slot * STAGE_B;
#pragma unroll
        for (int kk = 0; kk < 4; kk++) {
            uint32_t aH[2][4], bb[8][2];
#pragma unroll
            for (int mt = 0; mt < 2; mt++)
                ldm_x4(aH[mt][0], aH[mt][1], aH[mt][2], aH[mt][3],
                       st + aRowOfs + (uint32_t)mt * 16 * LDA + kk * 32);
#pragma unroll
            for (int p = 0; p < 4; p++)
                ldm_x4(bb[2 * p][0], bb[2 * p][1], bb[2 * p + 1][0], bb[2 * p + 1][1],
                       st + TILE_B + bRowOfs + (uint32_t)p * 16 * LDA + kk * 32);
#pragma unroll
            for (int mt = 0; mt < 2; mt++)
#pragma unroll
                for (int nt = 0; nt < 8; nt++) mma16816(acc[mt][nt], aH[mt], bb[nt]);
        }
        if (++slot == 3) slot = 0;
    }

    const int g = lane >> 2, t4 = lane & 3;
#pragma unroll
    for (int mt = 0; mt < 2; mt++) {
        float sA = 0.f, sB = 0.f;
#pragma unroll
        for (int nt = 0; nt < 8; nt++) {
            int c0 = n0 + wn * 64 + nt * 8 + 2 * t4;
            float b1a = b1[c0], b1b = b1[c0 + 1];
            float w2a = W2[c0], w2b = W2[c0 + 1];
            sA += fast_tanh(acc[mt][nt][0] + b1a) * w2a + fast_tanh(acc[mt][nt][1] + b1b) * w2b;
            sB += fast_tanh(acc[mt][nt][2] + b1a) * w2a + fast_tanh(acc[mt][nt][3] + b1b) * w2b;
        }
        sA += __shfl_xor_sync(0xFFFFFFFF, sA, 1);
        sA += __shfl_xor_sync(0xFFFFFFFF, sA, 2);
        sB += __shfl_xor_sync(0xFFFFFFFF, sB, 1);
        sB += __shfl_xor_sync(0xFFFFFFFF, sB, 2);
        if (t4 == 0) {
            int r = m0 + wm * 32 + mt * 16 + g;
            atomicAdd(&g_a[r], sA);
            atomicAdd(&g_a[r + 8], sB);
        }
    }
}

// ---------------- pool with in-block softmax (8 features per thread) ------
__global__ void pool_kernel() {
    int b = blockIdx.y;
    int t = threadIdx.x;
    int f0 = (blockIdx.x * 256 + t) * 8;
    __shared__ float sat[NW];
    __shared__ float red[NW];
    float v = 0.f;
    if (t < NW) { v = g_a[b * NW + t]; red[t] = v; }
    __syncthreads();
    for (int s = 64; s > 0; s >>= 1) { if (t < s) red[t] = fmaxf(red[t], red[t + s]); __syncthreads(); }
    float m = red[0];
    __syncthreads();
    float e = 0.f;
    if (t < NW) { e = expf(v - m); red[t] = e; }
    __syncthreads();
    for (int s = 64; s > 0; s >>= 1) { if (t < s) red[t] += red[t + s]; __syncthreads(); }
    if (t < NW) sat[t] = e / red[0];
    __syncthreads();
    if (f0 >= FEAT) return;
    float a[8];
#pragma unroll
    for (int j = 0; j < 8; j++) a[j] = 0.f;
    const char* base = (const char*)(g_bag + (size_t)b * NW * FEATP + f0);
#pragma unroll 2
    for (int w = 0; w < NW; w++) {
        float4 raw = *reinterpret_cast<const float4*>(base + (size_t)w * (FEATP * 2));
        const __half2* hp = reinterpret_cast<const __half2*>(&raw);
        float aw = sat[w];
#pragma unroll
        for (int j = 0; j < 4; j++) {
            float2 vv = __half22float2(hp[j]);
            a[2 * j]     += aw * vv.x;
            a[2 * j + 1] += aw * vv.y;
        }
    }
    float* dst = g_bagz0 + (size_t)b * FEATP + f0;
    if (f0 + 7 < FEAT) {
        *reinterpret_cast<float4*>(dst)     = make_float4(a[0], a[1], a[2], a[3]);
        *reinterpret_cast<float4*>(dst + 4) = make_float4(a[4], a[5], a[6], a[7]);
    } else {
#pragma unroll
        for (int j = 0; j < 8; j++)
            if (f0 + j < FEAT) dst[j] = a[j];
    }
}

// ---------------- batchnorms ----------------
__global__ void bn_kernel(const float* __restrict__ cc,
                          const float* __restrict__ bn_g, const float* __restrict__ bn_b,
                          const float* __restrict__ bn2_g, const float* __restrict__ bn2_b) {
    int f = blockIdx.x * 256 + threadIdx.x;
    if (f >= FEAT) return;
    float mu = 0.f;
    for (int b = 0; b < NB; b++) mu += g_bagz0[b * FEATP + f];
    mu *= (1.f / NB);
    float var = 0.f;
    for (int b = 0; b < NB; b++) { float d = g_bagz0[b * FEATP + f] - mu; var += d * d; }
    var *= (1.f / NB);
    float inv = rsqrtf(var + 1e-5f);
    float g = bn_g[f], bt = bn_b[f];
    for (int b = 0; b < NB; b++)
        g_bagz[b * FEATP + f] = (g_bagz0[b * FEATP + f] - mu) * inv * g + bt;
    float c0 = cc[f], c1 = cc[FEAT + f];
    float mu2 = 0.5f * (c0 + c1);
    float d0 = c0 - mu2, d1 = c1 - mu2;
    float inv2 = rsqrtf(0.5f * (d0 * d0 + d1 * d1) + 1e-5f);
    float g2 = bn2_g[f], b2v = bn2_b[f];
    g_ccn[f] = d0 * inv2 * g2 + b2v;
    g_ccn[FEATP + f] = d1 * inv2 * g2 + b2v;
}

// ---------------- dual skinny + kv (fused) --------------------------------
__global__ __launch_bounds__(256) void skinny_dual_kernel(const float* __restrict__ B1,
                                                          const float* __restrict__ B2,
                                                          const float* __restrict__ Wk) {
    __shared__ float sA[32][33];
    int tid = threadIdx.x;
    int col = blockIdx.x * 256 + tid;
    if (blockIdx.z == 2) {
        if (blockIdx.y >= 16) return;
        int len = (FEAT + 15) / 16;
        int k0 = blockIdx.y * len;
        int kend = min(FEAT, k0 + len);
        float ak0 = 0.f, ak1 = 0.f, av0 = 0.f, av1 = 0.f;
        for (int kb = k0; kb < kend; kb += 32) {
            int kmax = min(32, kend - kb);
            if (tid < 64) {
                int m = tid >> 5, kk = tid & 31;
                sA[m][kk] = (kk < kmax) ? g_ccn[(size_t)m * FEATP + kb + kk] : 0.f;
            }
            __syncthreads();
            const float* Kp = Wk + (size_t)kb * HH + col;
            const float* Qp = B1 + (size_t)kb * HH + col;
            int kk = 0;
            for (; kk + 2 <= kmax; kk += 2) {
                float k0v = Kp[0], k1v = Kp[HH];
                float q0v = Qp[0], q1v = Qp[HH];
                Kp += 2 * HH; Qp += 2 * HH;
                ak0 += sA[0][kk] * k0v; ak1 += sA[1][kk] * k0v;
                av0 += sA[0][kk] * q0v; av1 += sA[1][kk] * q0v;
                ak0 += sA[0][kk + 1] * k1v; ak1 += sA[1][kk + 1] * k1v;
                av0 += sA[0][kk + 1] * q1v; av1 += sA[1][kk + 1] * q1v;
            }
            for (; kk < kmax; kk++) {
                float kv = Kp[0], qv = Qp[0]; Kp += HH; Qp += HH;
                ak0 += sA[0][kk] * kv; ak1 += sA[1][kk] * kv;
                av0 += sA[0][kk] * qv; av1 += sA[1][kk] * qv;
            }
            __syncthreads();
        }
        atomicAdd(&g_k2[col], ak0);
        atomicAdd(&g_k2[HH + col], ak1);
        atomicAdd(&g_v2[col], av0);
        atomicAdd(&g_v2[HH + col], av1);
        return;
    }
    int m0 = blockIdx.z * 32;
    int nsplit = gridDim.y;
    int len = (FEAT + nsplit - 1) / nsplit;
    int k0 = blockIdx.y * len;
    int kend = min(FEAT, k0 + len);
    float aq[32], at[32];
#pragma unroll
    for (int m = 0; m < 32; m++) { aq[m] = 0.f; at[m] = 0.f; }
    for (int kb = k0; kb < kend; kb += 32) {
        int kmax = min(32, kend - kb);
        for (int idx = tid; idx < 32 * 32; idx += 256) {
            int m = idx >> 5, kk = idx & 31;
            sA[m][kk] = (kk < kmax) ? g_bagz[(size_t)(m0 + m) * FEATP + kb + kk] : 0.f;
        }
        __syncthreads();
        const float* P1 = B1 + (size_t)kb * HH + col;
        const float* P2 = B2 + (size_t)kb * DD + col;
        int kk = 0;
        for (; kk + 2 <= kmax; kk += 2) {
            float q0 = P1[0], q1 = P1[HH];
            float t0 = P2[0], t1v = P2[DD];
            P1 += 2 * HH; P2 += 2 * DD;
#pragma unroll
            for (int m = 0; m < 32; m++) aq[m] += sA[m][kk] * q0;
#pragma unroll
            for (int m = 0; m < 32; m++) at[m] += sA[m][kk] * t0;
#pragma unroll
            for (int m = 0; m < 32; m++) aq[m] += sA[m][kk + 1] * q1;
#pragma unroll
            for (int m = 0; m < 32; m++) at[m] += sA[m][kk + 1] * t1v;
        }
        for (; kk < kmax; kk++) {
            float q0 = P1[0], t0 = P2[0]; P1 += HH; P2 += DD;
#pragma unroll
            for (int m = 0; m < 32; m++) { aq[m] += sA[m][kk] * q0; at[m] += sA[m][kk] * t0; }
        }
        __syncthreads();
    }
#pragma unroll
    for (int m = 0; m < 32; m++) {
        atomicAdd(&g_q[(size_t)(m0 + m) * HH + col], aq[m]);
        atomicAdd(&g_t1[(size_t)(m0 + m) * DD + col], at[m]);
    }
}

// ---------------- fcx skinny with fused cross attention -------------------
// t1 += final_cross @ Wc1[0:HH], where final_cross[b] = a0[b]*v2 + a1[b]*v2'
// and (a0,a1) = softmax(q[b]·k2 / 32). Each block recomputes the 64 weight
// pairs in a prologue (warp w handles rows w*8..w*8+7).
__global__ __launch_bounds__(256) void skinny_fcx_kernel(const float* __restrict__ B) {
    __shared__ float sA[64][33];
    __shared__ float sw0[64], sw1[64];
    int tid = threadIdx.x, lane = tid & 31, wid = tid >> 5;
    int col = blockIdx.x * 256 + tid;
    // prologue: attention weights for 8 batch rows per warp
    for (int r = 0; r < 8; r++) {
        int b = wid * 8 + r;
        const float* qp = g_q + (size_t)b * HH;
        float d0 = 0.f, d1 = 0.f;
        for (int d = lane; d < HH; d += 32) {
            float qv = qp[d];
            d0 += qv * g_k2[d];
            d1 += qv * g_k2[HH + d];
        }
#pragma unroll
        for (int s = 16; s > 0; s >>= 1) {
            d0 += __shfl_xor_sync(0xFFFFFFFF, d0, s);
            d1 += __shfl_xor_sync(0xFFFFFFFF, d1, s);
        }
        if (lane == 0) {
            float x0 = d0 * (1.0f / 32.0f), x1 = d1 * (1.0f / 32.0f);
            float m = fmaxf(x0, x1);
            float e0 = expf(x0 - m), e1 = expf(x1 - m);
            float inv = 1.f / (e0 + e1);
            sw0[b] = e0 * inv;
            sw1[b] = e1 * inv;
        }
    }
    __syncthreads();

    int nsplit = gridDim.y;
    int len = (HH + nsplit - 1) / nsplit;
    int k0 = blockIdx.y * len;
    int kend = min(HH, k0 + len);
    float acc[64];
#pragma unroll
    for (int m = 0; m < 64; m++) acc[m] = 0.f;
    for (int kb = k0; kb < kend; kb += 32) {
        int kmax = min(32, kend - kb);
        for (int idx = tid; idx < 64 * 32; idx += 256) {
            int m = idx >> 5, kk = idx & 31;
            sA[m][kk] = (kk < kmax)
                ? sw0[m] * g_v2[kb + kk] + sw1[m] * g_v2[HH + kb + kk]
                : 0.f;
        }
        __syncthreads();
        const float* Bp = B + (size_t)kb * DD + col;
        int kk = 0;
        for (; kk + 4 <= kmax; kk += 4) {
            float bv0 = Bp[0];
            float bv1 = Bp[DD];
            float bv2 = Bp[2 * DD];
            float bv3 = Bp[3 * DD];
            Bp += 4 * (size_t)DD;
#pragma unroll
            for (int m = 0; m < 64; m++) acc[m] += sA[m][kk] * bv0;
#pragma unroll
            for (int m = 0; m < 64; m++) acc[m] += sA[m][kk + 1] * bv1;
#pragma unroll
            for (int m = 0; m < 64; m++) acc[m] += sA[m][kk + 2] * bv2;
#pragma unroll
            for (int m = 0; m < 64; m++) acc[m] += sA[m][kk + 3] * bv3;
        }
        for (; kk < kmax; kk++) {
            float bv = Bp[0]; Bp += (size_t)DD;
#pragma unroll
            for (int m = 0; m < 64; m++) acc[m] += sA[m][kk] * bv;
        }
        __syncthreads();
    }
#pragma unroll
    for (int m = 0; m < 64; m++) atomicAdd(&g_t1[(size_t)m * DD + col], acc[m]);
}

// ---------------- classifier head ----------------
__global__ void final_kernel(const float* __restrict__ Wc2, const float* __restrict__ bc2,
                             float* __restrict__ out, int out_size) {
    int b = blockIdx.x, t = threadIdx.x;
    float acc = 0.f;
    for (int d = t; d < DD; d += 256) acc += fmaxf(g_t1[b * DD + d], 0.f) * Wc2[d];
    __shared__ float red[256];
    red[t] = acc; __syncthreads();
    for (int s = 128; s > 0; s >>= 1) { if (t < s) red[t] += red[t + s]; __syncthreads(); }
    if (t == 0) {
        float y = 1.f / (1.f + expf(-(red[0] + bc2[0])));
        out[b] = y;
        if (64 + b < out_size) out[64 + b] = (y >= 0.5f) ? 1.f : 0.f;
    }
}

// ---------------- launch ----------------
extern "C" void kernel_launch(void* const* d_in, const int* in_sizes, int n_in,
                              void* d_out, int out_size) {
    const float* FC    = (const float*)d_in[0];
    const float* cc    = (const float*)d_in[1];
    const float* W1    = (const float*)d_in[2];
    const float* b1    = (const float*)d_in[3];
    const float* W2    = (const float*)d_in[4];
    const float* b2    = (const float*)d_in[5];
    const float* bn_g  = (const float*)d_in[6];
    const float* bn_b  = (const float*)d_in[7];
    const float* bn2_g = (const float*)d_in[8];
    const float* bn2_b = (const float*)d_in[9];
    const float* Wq    = (const float*)d_in[10];
    const float* bq    = (const float*)d_in[11];
    const float* Wk    = (const float*)d_in[12];
    const float* bk    = (const float*)d_in[13];
    const float* Wc1   = (const float*)d_in[14];
    const float* bc1   = (const float*)d_in[15];
    const float* Wc2   = (const float*)d_in[16];
    const float* bc2   = (const float*)d_in[17];
    float* out = (float*)d_out;

    cudaFuncSetAttribute(gemm_mma_kernel, cudaFuncAttributeMaxDynamicSharedMemorySize, GEMM_SMEM);

    init_off_kernel<<<ROI + INIT_BLOCKS, 256>>>(bq, bk, bc1);               // 1
    w1t_kernel<<<dim3(FEATP / 32, DD / 32), dim3(32, 8)>>>(W1, b2);         // 2
    gather_kernel<<<dim3(4, BW), 256>>>(FC);                                // 3
    gemm_mma_kernel<<<dim3(8, 64), 256, GEMM_SMEM>>>(b1, W2);               // 4 (ncu slot)
    pool_kernel<<<dim3(4, NB), 256>>>();
    bn_kernel<<<(FEAT + 255) / 256, 256>>>(cc, bn_g, bn_b, bn2_g, bn2_b);
    skinny_dual_kernel<<<dim3(4, 104, 3), 256>>>(Wq, Wc1 + (size_t)HH * DD, Wk);
    skinny_fcx_kernel<<<dim3(4, 16), 256>>>(Wc1);
    final_kernel<<<NB, 256>>>(Wc2, bc2, out, out_size);
}